// round 4
// baseline (speedup 1.0000x reference)
#include <cuda_runtime.h>
#include <cuda_bf16.h>
#include <cstdint>

#define NB      16384
#define OWN_D   7
#define INTR_D  5
#define NH      3
#define HD      5
#define NI      256
#define HID     256
#define IN_DIM  (OWN_D + NH*HD)        // 22
#define OBS_D   (OWN_D + NI*INTR_D)    // 1287

// attention output x = [own, context]
__device__ float g_x[NB * IN_DIM];
// W2 split into bf16 hi/lo, [n][k] layout (k contiguous)
__device__ __align__(16) __nv_bfloat16 g_w2hi[HID * HID];
__device__ __align__(16) __nv_bfloat16 g_w2lo[HID * HID];

// ---------------------------------------------------------------------------
// helpers
// ---------------------------------------------------------------------------
__device__ __forceinline__ uint32_t s2u(const void* p) {
    uint32_t a;
    asm("{ .reg .u64 t; cvta.to.shared.u64 t, %1; cvt.u32.u64 %0, t; }"
        : "=r"(a) : "l"(p));
    return a;
}
__device__ __forceinline__ void ldsm_x4(uint32_t* r, uint32_t addr) {
    asm volatile("ldmatrix.sync.aligned.m8n8.x4.shared.b16 {%0,%1,%2,%3}, [%4];"
        : "=r"(r[0]), "=r"(r[1]), "=r"(r[2]), "=r"(r[3]) : "r"(addr));
}
__device__ __forceinline__ void mma_bf16(float* d, const uint32_t* a,
                                         uint32_t b0, uint32_t b1) {
    asm volatile(
        "mma.sync.aligned.m16n8k16.row.col.f32.bf16.bf16.f32 "
        "{%0,%1,%2,%3}, {%4,%5,%6,%7}, {%8,%9}, {%0,%1,%2,%3};"
        : "+f"(d[0]), "+f"(d[1]), "+f"(d[2]), "+f"(d[3])
        : "r"(a[0]), "r"(a[1]), "r"(a[2]), "r"(a[3]), "r"(b0), "r"(b1));
}

// ---------------------------------------------------------------------------
// prep: W2 [k][n] fp32  ->  hi/lo bf16 [n][k]
// ---------------------------------------------------------------------------
__global__ void prep_w2_kernel(const float* __restrict__ W2) {
    const int n = blockIdx.x, k = threadIdx.x;
    const float w = W2[k * HID + n];
    const __nv_bfloat16 hi = __float2bfloat16(w);
    const float rem = w - __bfloat162float(hi);
    g_w2hi[n * HID + k] = hi;
    g_w2lo[n * HID + k] = __float2bfloat16(rem);
}

// ---------------------------------------------------------------------------
// Kernel A: additive attention (unchanged from R3)
// ---------------------------------------------------------------------------
__global__ void __launch_bounds__(128, 4) attn_kernel(
    const float* __restrict__ obs,
    const float* __restrict__ Wq, const float* __restrict__ bq,
    const float* __restrict__ Wk, const float* __restrict__ bk,
    const float* __restrict__ Wv, const float* __restrict__ bv,
    const float* __restrict__ v_att, const float* __restrict__ temperature)
{
    __shared__ float sWq[NH*HD*OWN_D];
    __shared__ float sWk[NH*HD*INTR_D];
    __shared__ float sWv[NH*HD*INTR_D];
    __shared__ float sbq[NH*HD], sbk[NH*HD], sbv[NH*HD], sva[NH*HD];

    const int tid = threadIdx.x;
    for (int i = tid; i < NH*HD*OWN_D;  i += 128) sWq[i] = Wq[i];
    for (int i = tid; i < NH*HD*INTR_D; i += 128) { sWk[i] = Wk[i]; sWv[i] = Wv[i]; }
    for (int i = tid; i < NH*HD;        i += 128) { sbq[i]=bq[i]; sbk[i]=bk[i]; sbv[i]=bv[i]; sva[i]=v_att[i]; }
    __syncthreads();

    const int warp = tid >> 5, lane = tid & 31;
    const int row  = blockIdx.x * 4 + warp;
    const float T  = fabsf(temperature[0]);
    const float* orow = obs + (size_t)row * OBS_D;

    float own[OWN_D];
    #pragma unroll
    for (int o = 0; o < OWN_D; o++) own[o] = __ldg(orow + o);

    float it[8][INTR_D];
    #pragma unroll
    for (int t = 0; t < 8; t++) {
        const float* p = orow + OWN_D + ((t << 5) + lane) * INTR_D;
        #pragma unroll
        for (int i = 0; i < INTR_D; i++) it[t][i] = __ldg(p + i);
    }
    float asum[8];
    #pragma unroll
    for (int t = 0; t < 8; t++)
        asum[t] = fabsf(it[t][0])+fabsf(it[t][1])+fabsf(it[t][2])
                 +fabsf(it[t][3])+fabsf(it[t][4]);

    constexpr float L2E2 = 2.885390082f;
    constexpr float L2E  = 1.442695041f;

    #pragma unroll
    for (int h = 0; h < NH; h++) {
        float wk[HD][INTR_D], qc[HD], va2t[HD];
        float sc0 = 0.0f;
        #pragma unroll
        for (int d = 0; d < HD; d++) {
            const int hd = h*HD + d;
            float q = sbq[hd] + sbk[hd];
            #pragma unroll
            for (int o = 0; o < OWN_D; o++) q = fmaf(own[o], sWq[hd*OWN_D + o], q);
            qc[d] = q;
            const float vaT = T * sva[hd];
            va2t[d] = 2.0f * vaT;
            sc0 += vaT - fabsf(vaT);
            #pragma unroll
            for (int i = 0; i < INTR_D; i++) wk[d][i] = sWk[hd*INTR_D + i];
        }

        float l = 0.0f, s0 = 0.f, s1 = 0.f, s2 = 0.f, s3 = 0.f, s4 = 0.f;

        #pragma unroll
        for (int t = 0; t < 8; t++) {
            const float x0 = it[t][0], x1 = it[t][1], x2 = it[t][2],
                        x3 = it[t][3], x4 = it[t][4];
            float sc = sc0;
            #pragma unroll
            for (int d = 0; d < HD; d++) {
                float k = qc[d];
                k = fmaf(x0, wk[d][0], k);
                k = fmaf(x1, wk[d][1], k);
                k = fmaf(x2, wk[d][2], k);
                k = fmaf(x3, wk[d][3], k);
                k = fmaf(x4, wk[d][4], k);
                const float e = exp2f(k * L2E2);
                const float r = __fdividef(1.0f, e + 1.0f);
                sc = fmaf(-va2t[d], r, sc);
            }
            float pw = exp2f(sc * L2E);
            if (asum[t] < 1e-6f) pw = 0.0f;

            l += pw;
            s0 = fmaf(pw, x0, s0);
            s1 = fmaf(pw, x1, s1);
            s2 = fmaf(pw, x2, s2);
            s3 = fmaf(pw, x3, s3);
            s4 = fmaf(pw, x4, s4);
        }

        #pragma unroll
        for (int off = 16; off > 0; off >>= 1) {
            l  += __shfl_xor_sync(0xffffffffu, l,  off);
            s0 += __shfl_xor_sync(0xffffffffu, s0, off);
            s1 += __shfl_xor_sync(0xffffffffu, s1, off);
            s2 += __shfl_xor_sync(0xffffffffu, s2, off);
            s3 += __shfl_xor_sync(0xffffffffu, s3, off);
            s4 += __shfl_xor_sync(0xffffffffu, s4, off);
        }

        if (lane == 0) {
            const float gate = (l > 0.0f) ? 1.0f : 0.0f;
            const float inv  = (l > 0.0f) ? __fdividef(1.0f, l) : 0.0f;
            const float t0 = s0*inv, t1 = s1*inv, t2 = s2*inv, t3 = s3*inv, t4 = s4*inv;
            #pragma unroll
            for (int d = 0; d < HD; d++) {
                const int hd = h*HD + d;
                float c = sbv[hd];
                c = fmaf(t0, sWv[hd*INTR_D + 0], c);
                c = fmaf(t1, sWv[hd*INTR_D + 1], c);
                c = fmaf(t2, sWv[hd*INTR_D + 2], c);
                c = fmaf(t3, sWv[hd*INTR_D + 3], c);
                c = fmaf(t4, sWv[hd*INTR_D + 4], c);
                g_x[(size_t)row*IN_DIM + OWN_D + hd] = c * gate;
            }
        }
    }

    if (lane < OWN_D) g_x[(size_t)row*IN_DIM + lane] = __ldg(orow + lane);
}

// ---------------------------------------------------------------------------
// Kernel B: tensor-core MLP.
//   x1 = leaky(x@W1+b1) computed per k-chunk (fp32), split to bf16 hi/lo.
//   x2 = leaky(x1@W2+b2) via split-bf16 mma.sync (3 MMAs), fp32 accumulate.
//   out = x2@Wf + bf fused in epilogue; log_std appended.
// CTA: 64 rows x 256 cols, 8 warps (2 m x 4 n). K chunk = 64.
// ---------------------------------------------------------------------------
#define SSTR   72                          // padded k-stride (bf16 elems)
#define OFF_A  (256*SSTR*2*2)              // 73728: after sBhi+sBlo
#define OFF_X  (OFF_A + 64*SSTR*2*2)       // 92160: after sAhi+sAlo
#define OFF_PO (OFF_X + 64*IN_DIM*4)       // 97792
#define SMEM_B_TOTAL (OFF_PO + 4*64*2*4)   // 99840

__global__ void __launch_bounds__(256, 2) mlp_tc_kernel(
    const float* __restrict__ W1, const float* __restrict__ b1,
    const float* __restrict__ b2, const float* __restrict__ Wf,
    const float* __restrict__ bf, const float* __restrict__ log_std,
    float* __restrict__ out)
{
    extern __shared__ __align__(16) char smem[];
    __nv_bfloat16* sBhi = (__nv_bfloat16*)smem;            // [256][72]
    __nv_bfloat16* sBlo = sBhi + 256*SSTR;
    __nv_bfloat16* sAhi = (__nv_bfloat16*)(smem + OFF_A);  // [64][72]
    __nv_bfloat16* sAlo = sAhi + 64*SSTR;
    float* sX  = (float*)(smem + OFF_X);                   // [64][22]
    float* sPO = (float*)(smem + OFF_PO);                  // [4][64][2]

    const int tid    = threadIdx.x;
    const int lane   = tid & 31;
    const int warp   = tid >> 5;
    const int warp_m = warp & 1;          // rows 32*warp_m .. +31
    const int warp_n = warp >> 1;         // cols 64*warp_n .. +63
    const int row0   = blockIdx.x * 64;

    for (int i = tid; i < 64*IN_DIM; i += 256)
        sX[i] = g_x[(size_t)row0 * IN_DIM + i];

    float acc[2][8][4];
    #pragma unroll
    for (int mt = 0; mt < 2; mt++)
        #pragma unroll
        for (int nt = 0; nt < 8; nt++)
            #pragma unroll
            for (int r = 0; r < 4; r++) acc[mt][nt][r] = 0.0f;

    const int xrow = tid & 63;            // x1 row this thread computes
    const int xcg  = tid >> 6;            // col group (16 cols)
    __syncthreads();

    // precompute ldmatrix lane offsets
    const int matq = lane >> 3, mrow = lane & 7;

    for (int ch = 0; ch < 4; ch++) {
        const int kk = ch * 64;

        // ---- stage W2 chunk: thread = n row, copy 64 bf16 (128B) hi+lo ----
        {
            const uint4* shi = (const uint4*)(g_w2hi + (size_t)tid*HID + kk);
            const uint4* slo = (const uint4*)(g_w2lo + (size_t)tid*HID + kk);
            uint4* dhi = (uint4*)(sBhi + tid*SSTR);
            uint4* dlo = (uint4*)(sBlo + tid*SSTR);
            #pragma unroll
            for (int u = 0; u < 8; u++) { dhi[u] = shi[u]; dlo[u] = slo[u]; }
        }

        // ---- compute x1 for (row=xrow, cols kk+16*xcg .. +15), split bf16 ----
        {
            const int co = kk + xcg*16;
            float a[16];
            #pragma unroll
            for (int j = 0; j < 16; j++) a[j] = __ldg(b1 + co + j);
            #pragma unroll
            for (int i = 0; i < IN_DIM; i++) {
                const float xv = sX[xrow*IN_DIM + i];
                const float4 w0 = *(const float4*)(W1 + (size_t)i*HID + co);
                const float4 w1 = *(const float4*)(W1 + (size_t)i*HID + co + 4);
                const float4 w2 = *(const float4*)(W1 + (size_t)i*HID + co + 8);
                const float4 w3 = *(const float4*)(W1 + (size_t)i*HID + co + 12);
                a[0]  = fmaf(xv, w0.x, a[0]);  a[1]  = fmaf(xv, w0.y, a[1]);
                a[2]  = fmaf(xv, w0.z, a[2]);  a[3]  = fmaf(xv, w0.w, a[3]);
                a[4]  = fmaf(xv, w1.x, a[4]);  a[5]  = fmaf(xv, w1.y, a[5]);
                a[6]  = fmaf(xv, w1.z, a[6]);  a[7]  = fmaf(xv, w1.w, a[7]);
                a[8]  = fmaf(xv, w2.x, a[8]);  a[9]  = fmaf(xv, w2.y, a[9]);
                a[10] = fmaf(xv, w2.z, a[10]); a[11] = fmaf(xv, w2.w, a[11]);
                a[12] = fmaf(xv, w3.x, a[12]); a[13] = fmaf(xv, w3.y, a[13]);
                a[14] = fmaf(xv, w3.z, a[14]); a[15] = fmaf(xv, w3.w, a[15]);
            }
            const int sbase = xrow*SSTR + xcg*16;
            #pragma unroll
            for (int j = 0; j < 16; j += 2) {
                float v0 = a[j];   v0 = (v0 > 0.0f) ? v0 : 0.2f*v0;
                float v1 = a[j+1]; v1 = (v1 > 0.0f) ? v1 : 0.2f*v1;
                const __nv_bfloat16 h0 = __float2bfloat16(v0);
                const __nv_bfloat16 h1 = __float2bfloat16(v1);
                const __nv_bfloat16 l0 = __float2bfloat16(v0 - __bfloat162float(h0));
                const __nv_bfloat16 l1 = __float2bfloat16(v1 - __bfloat162float(h1));
                const uint32_t uh = (uint32_t)__bfloat16_as_ushort(h0)
                                  | ((uint32_t)__bfloat16_as_ushort(h1) << 16);
                const uint32_t ul = (uint32_t)__bfloat16_as_ushort(l0)
                                  | ((uint32_t)__bfloat16_as_ushort(l1) << 16);
                *(uint32_t*)(sAhi + sbase + j) = uh;
                *(uint32_t*)(sAlo + sbase + j) = ul;
            }
        }
        __syncthreads();

        // ---- MMA over 4 k16 steps ----
        #pragma unroll
        for (int ks = 0; ks < 4; ks++) {
            const int k0 = ks * 16;

            uint32_t ahi[2][4], alo[2][4];
            #pragma unroll
            for (int mt = 0; mt < 2; mt++) {
                const int arow  = warp_m*32 + mt*16 + (matq & 1)*8 + mrow;
                const int akcol = k0 + (matq >> 1)*8;
                const int aoff  = arow*SSTR + akcol;
                ldsm_x4(ahi[mt], s2u(sAhi + aoff));
                ldsm_x4(alo[mt], s2u(sAlo + aoff));
            }

            #pragma unroll
            for (int np = 0; np < 4; np++) {
                const int brow  = warp_n*64 + np*16 + (matq >> 1)*8 + mrow;
                const int bkcol = k0 + (matq & 1)*8;
                const int boff  = brow*SSTR + bkcol;
                uint32_t bhi[4], blo[4];
                ldsm_x4(bhi, s2u(sBhi + boff));
                ldsm_x4(blo, s2u(sBlo + boff));

                #pragma unroll
                for (int mt = 0; mt < 2; mt++) {
                    float* d0 = acc[mt][np*2];
                    float* d1 = acc[mt][np*2 + 1];
                    mma_bf16(d0, ahi[mt], bhi[0], bhi[1]);
                    mma_bf16(d0, ahi[mt], blo[0], blo[1]);
                    mma_bf16(d0, alo[mt], bhi[0], bhi[1]);
                    mma_bf16(d1, ahi[mt], bhi[2], bhi[3]);
                    mma_bf16(d1, ahi[mt], blo[2], blo[3]);
                    mma_bf16(d1, alo[mt], bhi[2], bhi[3]);
                }
            }
        }
        __syncthreads();
    }

    // ---- epilogue: b2 + leaky + Wf projection, quad + cross-warp reduce ----
    float po[4][2];
    #pragma unroll
    for (int i = 0; i < 4; i++) { po[i][0] = 0.0f; po[i][1] = 0.0f; }

    #pragma unroll
    for (int nt = 0; nt < 8; nt++) {
        const int c = warp_n*64 + nt*8 + 2*(lane & 3);
        const float b2a = __ldg(b2 + c),       b2b = __ldg(b2 + c + 1);
        const float wa0 = __ldg(Wf + c*2),     wa1 = __ldg(Wf + c*2 + 1);
        const float wb0 = __ldg(Wf + c*2 + 2), wb1 = __ldg(Wf + c*2 + 3);
        #pragma unroll
        for (int mt = 0; mt < 2; mt++) {
            #pragma unroll
            for (int rr = 0; rr < 2; rr++) {
                float v0 = acc[mt][nt][rr*2]     + b2a;
                float v1 = acc[mt][nt][rr*2 + 1] + b2b;
                v0 = (v0 > 0.0f) ? v0 : 0.2f*v0;
                v1 = (v1 > 0.0f) ? v1 : 0.2f*v1;
                po[mt*2+rr][0] += v0*wa0 + v1*wb0;
                po[mt*2+rr][1] += v0*wa1 + v1*wb1;
            }
        }
    }

    #pragma unroll
    for (int off = 1; off <= 2; off <<= 1) {
        #pragma unroll
        for (int i = 0; i < 4; i++) {
            po[i][0] += __shfl_xor_sync(0xffffffffu, po[i][0], off);
            po[i][1] += __shfl_xor_sync(0xffffffffu, po[i][1], off);
        }
    }

    if ((lane & 3) == 0) {
        #pragma unroll
        for (int idx = 0; idx < 4; idx++) {
            const int mt = idx >> 1, rr = idx & 1;
            const int rl = warp_m*32 + mt*16 + rr*8 + (lane >> 2);
            sPO[(warp_n*64 + rl)*2 + 0] = po[idx][0];
            sPO[(warp_n*64 + rl)*2 + 1] = po[idx][1];
        }
    }
    __syncthreads();

    if (tid < 64) {
        float s0 = sPO[(0*64 + tid)*2]     + sPO[(1*64 + tid)*2]
                 + sPO[(2*64 + tid)*2]     + sPO[(3*64 + tid)*2];
        float s1 = sPO[(0*64 + tid)*2 + 1] + sPO[(1*64 + tid)*2 + 1]
                 + sPO[(2*64 + tid)*2 + 1] + sPO[(3*64 + tid)*2 + 1];
        float4 o;
        o.x = s0 + __ldg(bf + 0);
        o.y = s1 + __ldg(bf + 1);
        o.z = __ldg(log_std + 0);
        o.w = __ldg(log_std + 1);
        *(float4*)&out[(size_t)(row0 + tid)*4] = o;
    }
}

// ---------------------------------------------------------------------------
extern "C" void kernel_launch(void* const* d_in, const int* in_sizes, int n_in,
                              void* d_out, int out_size)
{
    const float* obs         = (const float*)d_in[0];
    const float* Wq          = (const float*)d_in[1];
    const float* bq          = (const float*)d_in[2];
    const float* Wk          = (const float*)d_in[3];
    const float* bk          = (const float*)d_in[4];
    const float* Wv          = (const float*)d_in[5];
    const float* bv          = (const float*)d_in[6];
    const float* v_att       = (const float*)d_in[7];
    const float* temperature = (const float*)d_in[8];
    const float* W1          = (const float*)d_in[9];
    const float* b1          = (const float*)d_in[10];
    const float* W2          = (const float*)d_in[11];
    const float* b2          = (const float*)d_in[12];
    const float* Wf          = (const float*)d_in[13];
    const float* bf          = (const float*)d_in[14];
    const float* log_std     = (const float*)d_in[15];
    float* out = (float*)d_out;

    cudaFuncSetAttribute(mlp_tc_kernel,
                         cudaFuncAttributeMaxDynamicSharedMemorySize,
                         SMEM_B_TOTAL);

    prep_w2_kernel<<<HID, HID>>>(W2);
    attn_kernel<<<NB/4, 128>>>(obs, Wq, bq, Wk, bk, Wv, bv, v_att, temperature);
    mlp_tc_kernel<<<NB/64, 256, SMEM_B_TOTAL>>>(W1, b1, b2, Wf, bf, log_std, out);
}

// round 7
// speedup vs baseline: 1.5929x; 1.5929x over previous
#include <cuda_runtime.h>
#include <cstdint>

#define NB      16384
#define OWN_D   7
#define INTR_D  5
#define NH      3
#define HD      5
#define NI      256
#define HID     256
#define IN_DIM  (OWN_D + NH*HD)        // 22
#define OBS_D   (OWN_D + NI*INTR_D)    // 1287

// attention output x = [own, context]
__device__ float g_x[NB * IN_DIM];

typedef unsigned long long ull;

// ---------------------------------------------------------------------------
// helpers
// ---------------------------------------------------------------------------
__device__ __forceinline__ uint32_t s2u(const void* p) {
    uint32_t a;
    asm("{ .reg .u64 t; cvta.to.shared.u64 t, %1; cvt.u32.u64 %0, t; }"
        : "=r"(a) : "l"(p));
    return a;
}
__device__ __forceinline__ void fma2(ull& d, ull a, ull b) {
    asm("fma.rn.f32x2 %0, %1, %2, %0;" : "+l"(d) : "l"(a), "l"(b));
}
__device__ __forceinline__ void unpack2(ull v, float& lo, float& hi) {
    asm("mov.b64 {%0, %1}, %2;" : "=f"(lo), "=f"(hi) : "l"(v));
}
__device__ __forceinline__ float tanh_fast(float x) {
    float r;
    asm("tanh.approx.f32 %0, %1;" : "=f"(r) : "f"(x));
    return r;
}
__device__ __forceinline__ void cp_async16(uint32_t dst, const void* src) {
    asm volatile("cp.async.cg.shared.global [%0], [%1], 16;"
                 :: "r"(dst), "l"(src) : "memory");
}
__device__ __forceinline__ void cp_commit() {
    asm volatile("cp.async.commit_group;" ::: "memory");
}
__device__ __forceinline__ void cp_wait0() {
    asm volatile("cp.async.wait_group 0;" ::: "memory");
}

// ---------------------------------------------------------------------------
// Kernel A: additive attention.  1 warp/row, 4 warps/CTA, 4 CTAs/SM.
// tanh via MUFU tanh.approx (1 MUFU instead of ex2+rcp).
// ---------------------------------------------------------------------------
__global__ void __launch_bounds__(128, 4) attn_kernel(
    const float* __restrict__ obs,
    const float* __restrict__ Wq, const float* __restrict__ bq,
    const float* __restrict__ Wk, const float* __restrict__ bk,
    const float* __restrict__ Wv, const float* __restrict__ bv,
    const float* __restrict__ v_att, const float* __restrict__ temperature)
{
    __shared__ float sWq[NH*HD*OWN_D];
    __shared__ float sWk[NH*HD*INTR_D];
    __shared__ float sWv[NH*HD*INTR_D];
    __shared__ float sbq[NH*HD], sbk[NH*HD], sbv[NH*HD], sva[NH*HD];

    const int tid = threadIdx.x;
    for (int i = tid; i < NH*HD*OWN_D;  i += 128) sWq[i] = Wq[i];
    for (int i = tid; i < NH*HD*INTR_D; i += 128) { sWk[i] = Wk[i]; sWv[i] = Wv[i]; }
    for (int i = tid; i < NH*HD;        i += 128) { sbq[i]=bq[i]; sbk[i]=bk[i]; sbv[i]=bv[i]; sva[i]=v_att[i]; }
    __syncthreads();

    const int warp = tid >> 5, lane = tid & 31;
    const int row  = blockIdx.x * 4 + warp;
    const float T  = fabsf(temperature[0]);
    const float* orow = obs + (size_t)row * OBS_D;

    float own[OWN_D];
    #pragma unroll
    for (int o = 0; o < OWN_D; o++) own[o] = __ldg(orow + o);

    float it[8][INTR_D];
    #pragma unroll
    for (int t = 0; t < 8; t++) {
        const float* p = orow + OWN_D + ((t << 5) + lane) * INTR_D;
        #pragma unroll
        for (int i = 0; i < INTR_D; i++) it[t][i] = __ldg(p + i);
    }
    float asum[8];
    #pragma unroll
    for (int t = 0; t < 8; t++)
        asum[t] = fabsf(it[t][0])+fabsf(it[t][1])+fabsf(it[t][2])
                 +fabsf(it[t][3])+fabsf(it[t][4]);

    constexpr float L2E = 1.442695041f;

    #pragma unroll
    for (int h = 0; h < NH; h++) {
        float wk[HD][INTR_D], qc[HD], vaT[HD];
        float shift = 0.0f;
        #pragma unroll
        for (int d = 0; d < HD; d++) {
            const int hd = h*HD + d;
            float q = sbq[hd] + sbk[hd];
            #pragma unroll
            for (int o = 0; o < OWN_D; o++) q = fmaf(own[o], sWq[hd*OWN_D + o], q);
            qc[d]  = q;
            vaT[d] = T * sva[hd];
            shift += fabsf(vaT[d]);          // score upper bound -> pw <= 1
            #pragma unroll
            for (int i = 0; i < INTR_D; i++) wk[d][i] = sWk[hd*INTR_D + i];
        }

        float l = 0.0f, s0 = 0.f, s1 = 0.f, s2 = 0.f, s3 = 0.f, s4 = 0.f;

        #pragma unroll
        for (int t = 0; t < 8; t++) {
            const float x0 = it[t][0], x1 = it[t][1], x2 = it[t][2],
                        x3 = it[t][3], x4 = it[t][4];
            float sc = -shift;
            #pragma unroll
            for (int d = 0; d < HD; d++) {
                float k = qc[d];
                k = fmaf(x0, wk[d][0], k);
                k = fmaf(x1, wk[d][1], k);
                k = fmaf(x2, wk[d][2], k);
                k = fmaf(x3, wk[d][3], k);
                k = fmaf(x4, wk[d][4], k);
                sc = fmaf(vaT[d], tanh_fast(k), sc);
            }
            float pw = exp2f(sc * L2E);
            if (asum[t] < 1e-6f) pw = 0.0f;

            l += pw;
            s0 = fmaf(pw, x0, s0);
            s1 = fmaf(pw, x1, s1);
            s2 = fmaf(pw, x2, s2);
            s3 = fmaf(pw, x3, s3);
            s4 = fmaf(pw, x4, s4);
        }

        #pragma unroll
        for (int off = 16; off > 0; off >>= 1) {
            l  += __shfl_xor_sync(0xffffffffu, l,  off);
            s0 += __shfl_xor_sync(0xffffffffu, s0, off);
            s1 += __shfl_xor_sync(0xffffffffu, s1, off);
            s2 += __shfl_xor_sync(0xffffffffu, s2, off);
            s3 += __shfl_xor_sync(0xffffffffu, s3, off);
            s4 += __shfl_xor_sync(0xffffffffu, s4, off);
        }

        if (lane == 0) {
            const float gate = (l > 0.0f) ? 1.0f : 0.0f;
            const float inv  = (l > 0.0f) ? __fdividef(1.0f, l) : 0.0f;
            const float t0 = s0*inv, t1 = s1*inv, t2 = s2*inv, t3 = s3*inv, t4 = s4*inv;
            #pragma unroll
            for (int d = 0; d < HD; d++) {
                const int hd = h*HD + d;
                float c = sbv[hd];
                c = fmaf(t0, sWv[hd*INTR_D + 0], c);
                c = fmaf(t1, sWv[hd*INTR_D + 1], c);
                c = fmaf(t2, sWv[hd*INTR_D + 2], c);
                c = fmaf(t3, sWv[hd*INTR_D + 3], c);
                c = fmaf(t4, sWv[hd*INTR_D + 4], c);
                g_x[(size_t)row*IN_DIM + OWN_D + hd] = c * gate;
            }
        }
    }

    if (lane < OWN_D) g_x[(size_t)row*IN_DIM + lane] = __ldg(orow + lane);
}

// ---------------------------------------------------------------------------
// Kernel B: fused MLP (FFMA2, zero-pack inner loop).
// CTA = 64 rows x 256 cols, 256 threads.
// thread microtile: 8 rows x 8 cols as 8x4 packed f32x2 accumulators.
// x1 stored DUPLICATED in smem -> both FFMA2 operands load directly.
// W2 chunks double-buffered via cp.async; x1 double-buffered; 1 sync/chunk.
// ---------------------------------------------------------------------------
#define X1STR  132                           // padded dup-row stride (floats)
#define OFF_W2 0                             // [2][32*256] f32 = 65536 B
#define OFF_X1 65536                         // [2][32*X1STR] f32 = 33792 B
#define OFF_SX (65536 + 33792)               // [64*22] f32 = 5632 B
#define SMEM_MLP (OFF_SX + 5632)             // 104960 B

__global__ void __launch_bounds__(256, 2) mlp_kernel(
    const float* __restrict__ W1, const float* __restrict__ b1,
    const float* __restrict__ W2, const float* __restrict__ b2,
    const float* __restrict__ Wf, const float* __restrict__ bf,
    const float* __restrict__ log_std, float* __restrict__ out)
{
    extern __shared__ __align__(16) char dsm[];
    float* sW2 = (float*)(dsm + OFF_W2);     // [2][32][256]
    float* sX1 = (float*)(dsm + OFF_X1);     // [2][32][X1STR] duplicated
    float* sX  = (float*)(dsm + OFF_SX);     // [64][22]
    const uint32_t w2b = s2u(sW2);

    const int tid  = threadIdx.x;
    const int ct   = tid & 31;               // col-thread / lane
    const int rg   = tid >> 5;               // row-group / warp
    const int c0   = ct * 8;
    const int r0   = rg * 8;
    const int row0 = blockIdx.x * 64;

    // prefetch W2 chunk 0
    #pragma unroll
    for (int u = 0; u < 8; u++) {
        const int idx = u*256 + tid;
        cp_async16(w2b + idx*16, W2 + idx*4);
    }
    cp_commit();

    // stage x
    for (int i = tid; i < 64*IN_DIM; i += 256)
        sX[i] = g_x[(size_t)row0*IN_DIM + i];
    __syncthreads();

    ull acc[8][4];
    #pragma unroll
    for (int j = 0; j < 8; j++)
        #pragma unroll
        for (int p = 0; p < 4; p++) acc[j][p] = 0ULL;

    for (int ch = 0; ch < 8; ch++) {
        const int kk  = ch * 32;
        const int buf = ch & 1;

        // ---- x1 for column kk+ct, rows r0..r0+7 (write duplicated) ----
        {
            float a[8];
            const float bb = __ldg(b1 + kk + ct);
            #pragma unroll
            for (int j = 0; j < 8; j++) a[j] = bb;
            const float* w1c = W1 + kk + ct;
            #pragma unroll
            for (int i = 0; i < IN_DIM; i++) {
                const float wv = __ldg(w1c + i*HID);
                const float* xr = sX + r0*IN_DIM + i;
                #pragma unroll
                for (int j = 0; j < 8; j++)
                    a[j] = fmaf(xr[j*IN_DIM], wv, a[j]);
            }
            float* xd = sX1 + buf*(32*X1STR) + ct*X1STR;
            #pragma unroll
            for (int j = 0; j < 8; j++) {
                float v = a[j];
                v = (v > 0.0f) ? v : 0.2f * v;
                *(float2*)&xd[2*(r0 + j)] = make_float2(v, v);
            }
        }

        cp_wait0();            // W2 chunk ch has landed
        __syncthreads();       // x1[buf] + W2[buf] visible to all

        // prefetch next W2 chunk into the other buffer (overlaps FFMA2 loop)
        if (ch < 7) {
            const uint32_t dst = w2b + (buf ^ 1)*32768;
            const float* src = W2 + (size_t)(kk + 32)*HID;
            #pragma unroll
            for (int u = 0; u < 8; u++) {
                const int idx = u*256 + tid;
                cp_async16(dst + idx*16, src + idx*4);
            }
            cp_commit();
        }

        // ---- FFMA2 inner loop ----
        const float* Wb = sW2 + buf*8192;
        const float* Xb = sX1 + buf*(32*X1STR);
        #pragma unroll 4
        for (int k = 0; k < 32; k++) {
            const ulonglong2* xp = (const ulonglong2*)(Xb + k*X1STR + 2*r0);
            const ulonglong2 xa = xp[0], xb_ = xp[1], xc = xp[2], xd_ = xp[3];
            const ulonglong2* wp = (const ulonglong2*)(Wb + k*256 + c0);
            const ulonglong2 wa = wp[0], wb_ = wp[1];

            fma2(acc[0][0], xa.x,  wa.x);  fma2(acc[0][1], xa.x,  wa.y);
            fma2(acc[0][2], xa.x,  wb_.x); fma2(acc[0][3], xa.x,  wb_.y);
            fma2(acc[1][0], xa.y,  wa.x);  fma2(acc[1][1], xa.y,  wa.y);
            fma2(acc[1][2], xa.y,  wb_.x); fma2(acc[1][3], xa.y,  wb_.y);
            fma2(acc[2][0], xb_.x, wa.x);  fma2(acc[2][1], xb_.x, wa.y);
            fma2(acc[2][2], xb_.x, wb_.x); fma2(acc[2][3], xb_.x, wb_.y);
            fma2(acc[3][0], xb_.y, wa.x);  fma2(acc[3][1], xb_.y, wa.y);
            fma2(acc[3][2], xb_.y, wb_.x); fma2(acc[3][3], xb_.y, wb_.y);
            fma2(acc[4][0], xc.x,  wa.x);  fma2(acc[4][1], xc.x,  wa.y);
            fma2(acc[4][2], xc.x,  wb_.x); fma2(acc[4][3], xc.x,  wb_.y);
            fma2(acc[5][0], xc.y,  wa.x);  fma2(acc[5][1], xc.y,  wa.y);
            fma2(acc[5][2], xc.y,  wb_.x); fma2(acc[5][3], xc.y,  wb_.y);
            fma2(acc[6][0], xd_.x, wa.x);  fma2(acc[6][1], xd_.x, wa.y);
            fma2(acc[6][2], xd_.x, wb_.x); fma2(acc[6][3], xd_.x, wb_.y);
            fma2(acc[7][0], xd_.y, wa.x);  fma2(acc[7][1], xd_.y, wa.y);
            fma2(acc[7][2], xd_.y, wb_.x); fma2(acc[7][3], xd_.y, wb_.y);
        }
    }

    // ---- epilogue: b2 + leaky + Wf projection ----
    float po0[8], po1[8];
    #pragma unroll
    for (int j = 0; j < 8; j++) { po0[j] = 0.0f; po1[j] = 0.0f; }

    #pragma unroll
    for (int p = 0; p < 4; p++) {
        const int c = c0 + 2*p;
        const float b2a = __ldg(b2 + c),       b2b = __ldg(b2 + c + 1);
        const float wa0 = __ldg(Wf + c*2),     wa1 = __ldg(Wf + c*2 + 1);
        const float wb0 = __ldg(Wf + c*2 + 2), wb1 = __ldg(Wf + c*2 + 3);
        #pragma unroll
        for (int j = 0; j < 8; j++) {
            float vl, vh;
            unpack2(acc[j][p], vl, vh);
            vl += b2a; vl = (vl > 0.0f) ? vl : 0.2f*vl;
            vh += b2b; vh = (vh > 0.0f) ? vh : 0.2f*vh;
            po0[j] += vl*wa0 + vh*wb0;
            po1[j] += vl*wa1 + vh*wb1;
        }
    }

    #pragma unroll
    for (int off = 16; off > 0; off >>= 1) {
        #pragma unroll
        for (int j = 0; j < 8; j++) {
            po0[j] += __shfl_xor_sync(0xffffffffu, po0[j], off);
            po1[j] += __shfl_xor_sync(0xffffffffu, po1[j], off);
        }
    }

    if (ct == 0) {
        const float bf0 = __ldg(bf + 0), bf1 = __ldg(bf + 1);
        const float ls0 = __ldg(log_std + 0), ls1 = __ldg(log_std + 1);
        #pragma unroll
        for (int j = 0; j < 8; j++) {
            float4 o;
            o.x = po0[j] + bf0;
            o.y = po1[j] + bf1;
            o.z = ls0;
            o.w = ls1;
            *(float4*)&out[(size_t)(row0 + r0 + j)*4] = o;
        }
    }
}

// ---------------------------------------------------------------------------
extern "C" void kernel_launch(void* const* d_in, const int* in_sizes, int n_in,
                              void* d_out, int out_size)
{
    const float* obs         = (const float*)d_in[0];
    const float* Wq          = (const float*)d_in[1];
    const float* bq          = (const float*)d_in[2];
    const float* Wk          = (const float*)d_in[3];
    const float* bk          = (const float*)d_in[4];
    const float* Wv          = (const float*)d_in[5];
    const float* bv          = (const float*)d_in[6];
    const float* v_att       = (const float*)d_in[7];
    const float* temperature = (const float*)d_in[8];
    const float* W1          = (const float*)d_in[9];
    const float* b1          = (const float*)d_in[10];
    const float* W2          = (const float*)d_in[11];
    const float* b2          = (const float*)d_in[12];
    const float* Wf          = (const float*)d_in[13];
    const float* bf          = (const float*)d_in[14];
    const float* log_std     = (const float*)d_in[15];
    float* out = (float*)d_out;

    static int smem_set = 0;
    if (!smem_set) {
        cudaFuncSetAttribute(mlp_kernel,
                             cudaFuncAttributeMaxDynamicSharedMemorySize,
                             SMEM_MLP);
        smem_set = 1;
    }

    attn_kernel<<<NB/4, 128>>>(obs, Wq, bq, Wk, bk, Wv, bv, v_att, temperature);
    mlp_kernel<<<NB/64, 256, SMEM_MLP>>>(W1, b1, W2, b2, Wf, bf, log_std, out);
}